// round 14
// baseline (speedup 1.0000x reference)
#include <cuda_runtime.h>
#include <cstdint>

#define BATCH  512
#define NELEC  32
#define NALL   36
#define NNUC   4
#define BASIS  32
#define KDIM   128
#define EDIM   128
#define HIDK   64
#define HIDO   128

// ---------------- scratch (device globals; no runtime allocation) ----------
__device__ float g_xs[BATCH * NELEC * EDIM];          // fp32 residual stream
__device__ float g_zs[BATCH * NALL * KDIM];           // fp32 zs (zj reads)
// packed bf16x2 plane buffers (hi/lo)
__device__ __align__(16) unsigned g_zh[BATCH * NELEC * 64];
__device__ __align__(16) unsigned g_zl[BATCH * NELEC * 64];
__device__ __align__(16) unsigned g_eh[32 * 64];
__device__ __align__(16) unsigned g_el[32 * 64];
__device__ __align__(16) unsigned g_winh[3 * 128 * 64];
__device__ __align__(16) unsigned g_winl[3 * 128 * 64];
__device__ __align__(16) unsigned g_wo1h[3 * 128 * 64];
__device__ __align__(16) unsigned g_wo1l[3 * 128 * 64];
__device__ __align__(16) unsigned g_wo2h[3 * 128 * 64];
__device__ __align__(16) unsigned g_wo2l[3 * 128 * 64];
__device__ __align__(16) unsigned g_w1h[3 * 64 * 16];   // plain layout
__device__ __align__(16) unsigned g_w1l[3 * 64 * 16];
__device__ __align__(16) unsigned g_w2h[3 * 128 * 32];  // plain layout
__device__ __align__(16) unsigned g_w2l[3 * 128 * 32];

__device__ __forceinline__ float sspf(float x) {
    float e = __expf(-fabsf(x));
    float l = __logf(1.0f + e);
    return fmaxf(x, 0.0f) + l - 0.69314718055994530942f;
}

// ---------------- bf16 MMA helpers ----------------
__device__ __forceinline__ void mma_bf16(float* c, const unsigned* a, const unsigned* b) {
    asm volatile("mma.sync.aligned.m16n8k16.row.col.f32.bf16.bf16.f32 "
        "{%0,%1,%2,%3}, {%4,%5,%6,%7}, {%8,%9}, {%0,%1,%2,%3};"
        : "+f"(c[0]), "+f"(c[1]), "+f"(c[2]), "+f"(c[3])
        : "r"(a[0]), "r"(a[1]), "r"(a[2]), "r"(a[3]), "r"(b[0]), "r"(b[1]));
}
__device__ __forceinline__ void mma3(float* c, const unsigned* ah, const unsigned* al,
                                     const unsigned* bh, const unsigned* bl) {
    mma_bf16(c, ah, bh);
    mma_bf16(c, al, bh);
    mma_bf16(c, ah, bl);
}
// term-split: 3 independent accumulator chains
__device__ __forceinline__ void mma3t(float* cP, float* cQ, float* cR,
                                      const unsigned* ah, const unsigned* al,
                                      const unsigned* bh, const unsigned* bl) {
    mma_bf16(cP, ah, bh);
    mma_bf16(cQ, al, bh);
    mma_bf16(cR, ah, bl);
}
__device__ __forceinline__ unsigned pack_bf16(float f0, float f1) {
    unsigned r;
    asm("cvt.rn.bf16x2.f32 %0, %1, %2;" : "=r"(r) : "f"(f1), "f"(f0));
    return r;
}
__device__ __forceinline__ void split2(float f0, float f1, unsigned &hi, unsigned &lo) {
    hi = pack_bf16(f0, f1);
    float h0 = __uint_as_float(hi << 16);
    float h1 = __uint_as_float(hi & 0xFFFF0000u);
    lo = pack_bf16(f0 - h0, f1 - h1);
}
__device__ __forceinline__ void ldm_x4(unsigned* r, const void* p) {
    unsigned a = (unsigned)__cvta_generic_to_shared(p);
    asm volatile("ldmatrix.sync.aligned.m8n8.x4.shared.b16 {%0,%1,%2,%3}, [%4];"
                 : "=r"(r[0]), "=r"(r[1]), "=r"(r[2]), "=r"(r[3]) : "r"(a));
}

// packed-plane B fragment
__device__ __forceinline__ void bfrag_pk(const unsigned* Wh, const unsigned* Wl,
                                         int n, int kt, int t,
                                         unsigned* bh, unsigned* bl) {
    uint2 uh = *(const uint2*)&Wh[n * 64 + kt * 8 + 2 * t];
    uint2 ul = *(const uint2*)&Wl[n * 64 + kt * 8 + 2 * t];
    bh[0] = uh.x; bh[1] = uh.y;
    bl[0] = ul.x; bl[1] = ul.y;
}
// packed-plane A fragment (ldw = words/row)
__device__ __forceinline__ void afrag_pk(const unsigned* Ah, const unsigned* Al,
                                         int r, int kt, int t, int ldw,
                                         unsigned* ah, unsigned* al) {
    uint2 uh0 = *(const uint2*)&Ah[r * ldw + kt * 8 + 2 * t];
    uint2 uh1 = *(const uint2*)&Ah[(r + 8) * ldw + kt * 8 + 2 * t];
    uint2 ul0 = *(const uint2*)&Al[r * ldw + kt * 8 + 2 * t];
    uint2 ul1 = *(const uint2*)&Al[(r + 8) * ldw + kt * 8 + 2 * t];
    ah[0] = uh0.x; ah[2] = uh0.y; ah[1] = uh1.x; ah[3] = uh1.y;
    al[0] = ul0.x; al[2] = ul0.y; al[1] = ul1.x; al[3] = ul1.y;
}

// ---------------------------------------------------------------------------
// single fused prep kernel
// ---------------------------------------------------------------------------
__device__ __forceinline__ void pack_plain_one(const float* src, unsigned* dh,
                                               unsigned* dl, int idx) {
    unsigned hi, lo;
    split2(src[2 * idx], src[2 * idx + 1], hi, lo);
    dh[idx] = hi; dl[idx] = lo;
}
__device__ __forceinline__ void pack_perm_one(const float* src, unsigned* dh,
                                              unsigned* dl, int idx, int cwords) {
    int r = idx / cwords, w = idx - r * cwords;
    int kt = w >> 3, i = w & 7, t = i >> 1, h = i & 1;
    int c0 = kt * 16 + 2 * t + 8 * h;
    const float* row = src + (long)r * (cwords * 2);
    unsigned hi, lo;
    split2(row[c0], row[c0 + 1], hi, lo);
    dh[idx] = hi; dl[idx] = lo;
}

__global__ void pack_all_kernel(
    const float* __restrict__ w1, const float* __restrict__ w2,
    const float* __restrict__ emb_e,
    const float* __restrict__ win, const float* __restrict__ wo1,
    const float* __restrict__ wo2, const float* __restrict__ emb_n,
    unsigned* __restrict__ w1h, unsigned* __restrict__ w1l,
    unsigned* __restrict__ w2h, unsigned* __restrict__ w2l,
    unsigned* __restrict__ eh, unsigned* __restrict__ el,
    unsigned* __restrict__ winh, unsigned* __restrict__ winl,
    unsigned* __restrict__ wo1h, unsigned* __restrict__ wo1l,
    unsigned* __restrict__ wo2h, unsigned* __restrict__ wo2l,
    float* __restrict__ zs)
{
    int idx = blockIdx.x * blockDim.x + threadIdx.x;
    if (idx < 3072) { pack_plain_one(w1, w1h, w1l, idx); return; }
    idx -= 3072;
    if (idx < 12288) { pack_plain_one(w2, w2h, w2l, idx); return; }
    idx -= 12288;
    if (idx < 2048) { pack_perm_one(emb_e, eh, el, idx, 64); return; }
    idx -= 2048;
    if (idx < 24576) { pack_perm_one(win, winh, winl, idx, 64); return; }
    idx -= 24576;
    if (idx < 24576) { pack_perm_one(wo1, wo1h, wo1l, idx, 64); return; }
    idx -= 24576;
    if (idx < 24576) { pack_perm_one(wo2, wo2h, wo2l, idx, 64); return; }
    idx -= 24576;
    if (idx < BATCH * NNUC * KDIM) {
        int d = idx & 127;
        int m = (idx >> 7) & 3;
        int b = idx >> 9;
        zs[(b * NALL + NELEC + m) * KDIM + d] = emb_n[m * KDIM + d];
    }
}
#define PACK_ALL_TOTAL (3072 + 12288 + 2048 + 3 * 24576 + BATCH * NNUC * KDIM)

// ---------------------------------------------------------------------------
// zs linear for t=0 (unchanged — passing)
// ---------------------------------------------------------------------------
__global__ __launch_bounds__(256) void zslin_first_kernel(
    const unsigned* __restrict__ eh, const unsigned* __restrict__ el,
    const unsigned* __restrict__ wh, const unsigned* __restrict__ wl,
    float* __restrict__ zs)
{
    int b = blockIdx.x;
    int tid = threadIdx.x;
    int wid = tid >> 5, lane = tid & 31;
    int g = lane >> 2, t = lane & 3;
    int n0 = wid * 16;

    float c[2][2][4];
#pragma unroll
    for (int mi = 0; mi < 2; mi++)
#pragma unroll
        for (int nj = 0; nj < 2; nj++)
#pragma unroll
            for (int q = 0; q < 4; q++) c[mi][nj][q] = 0.f;

#pragma unroll
    for (int kt = 0; kt < 8; kt++) {
        unsigned ah[2][4], al[2][4];
#pragma unroll
        for (int mi = 0; mi < 2; mi++)
            afrag_pk(eh, el, mi * 16 + g, kt, t, 64, ah[mi], al[mi]);
#pragma unroll
        for (int nj = 0; nj < 2; nj++) {
            unsigned bh[2], bl[2];
            bfrag_pk(wh, wl, n0 + nj * 8 + g, kt, t, bh, bl);
#pragma unroll
            for (int mi = 0; mi < 2; mi++)
                mma3(c[mi][nj], ah[mi], al[mi], bh, bl);
        }
    }
#pragma unroll
    for (int mi = 0; mi < 2; mi++)
#pragma unroll
        for (int nj = 0; nj < 2; nj++) {
            int r = mi * 16 + g;
            int k = n0 + nj * 8 + 2 * t;
            *(float2*)&zs[(b * NALL + r) * 128 + k] = make_float2(c[mi][nj][0], c[mi][nj][1]);
            *(float2*)&zs[(b * NALL + r + 8) * 128 + k] = make_float2(c[mi][nj][2], c[mi][nj][3]);
        }
}

// ---------------------------------------------------------------------------
// Fused out-MLP: 2 batch samples per CTA (grid = BATCH/2).
// mi 0..3: sample s=mi>>1 (b0+s), tile mt=mi&1. Hs rows: s*32 + local row.
// ---------------------------------------------------------------------------
template <bool FIRST, bool WRITE_ZS>
__global__ __launch_bounds__(256) void outmlp_mma_kernel(
    const unsigned* __restrict__ zh, const unsigned* __restrict__ zl,
    const unsigned* __restrict__ wo1h, const unsigned* __restrict__ wo1l,
    const float* __restrict__ bo1,
    const unsigned* __restrict__ wo2h, const unsigned* __restrict__ wo2l,
    const float* __restrict__ bo2,
    const float* __restrict__ res, float* __restrict__ out,
    const unsigned* __restrict__ winh, const unsigned* __restrict__ winl,
    float* __restrict__ zs)
{
    __shared__ unsigned short Hs[2][64][136];

    int b0 = blockIdx.x * 2;
    int tid = threadIdx.x;
    int wid = tid >> 5, lane = tid & 31;
    int g = lane >> 2, t = lane & 3;
    int lr = lane & 7, lm = lane >> 3;
    int n0 = wid * 16;

    // ---- GEMM1: z @ Wo1^T (both samples) ----
    float c[4][2][4];
#pragma unroll
    for (int mi = 0; mi < 4; mi++)
#pragma unroll
        for (int nj = 0; nj < 2; nj++)
#pragma unroll
            for (int q = 0; q < 4; q++) c[mi][nj][q] = 0.f;

#pragma unroll
    for (int kt = 0; kt < 8; kt++) {
        unsigned ah[4][4], al[4][4];
#pragma unroll
        for (int mi = 0; mi < 4; mi++) {
            int s = mi >> 1, mt = mi & 1;
            afrag_pk(zh + (long)(b0 + s) * 2048, zl + (long)(b0 + s) * 2048,
                     mt * 16 + g, kt, t, 64, ah[mi], al[mi]);
        }
#pragma unroll
        for (int nj = 0; nj < 2; nj++) {
            unsigned bh[2], bl[2];
            bfrag_pk(wo1h, wo1l, n0 + nj * 8 + g, kt, t, bh, bl);
#pragma unroll
            for (int mi = 0; mi < 4; mi++)
                mma3(c[mi][nj], ah[mi], al[mi], bh, bl);
        }
    }

    // ---- epi1: +bo1, ssp, split -> Hs ----
#pragma unroll
    for (int mi = 0; mi < 4; mi++)
#pragma unroll
        for (int nj = 0; nj < 2; nj++) {
            int s = mi >> 1, mt = mi & 1;
            int R = s * 32 + mt * 16 + g;
            int k = n0 + nj * 8 + 2 * t;
            float2 bb = *(const float2*)&bo1[k];
            unsigned hi, lo;
            split2(sspf(c[mi][nj][0] + bb.x), sspf(c[mi][nj][1] + bb.y), hi, lo);
            *(unsigned*)&Hs[0][R][k] = hi;
            *(unsigned*)&Hs[1][R][k] = lo;
            split2(sspf(c[mi][nj][2] + bb.x), sspf(c[mi][nj][3] + bb.y), hi, lo);
            *(unsigned*)&Hs[0][R + 8][k] = hi;
            *(unsigned*)&Hs[1][R + 8][k] = lo;
        }
    __syncthreads();

    // ---- GEMM2: h @ Wo2^T ----
    float d[4][2][4];
#pragma unroll
    for (int mi = 0; mi < 4; mi++)
#pragma unroll
        for (int nj = 0; nj < 2; nj++)
#pragma unroll
            for (int q = 0; q < 4; q++) d[mi][nj][q] = 0.f;

#pragma unroll
    for (int kt = 0; kt < 8; kt++) {
        unsigned ah[4][4], al[4][4];
#pragma unroll
        for (int mi = 0; mi < 4; mi++) {
            int s = mi >> 1, mt = mi & 1;
            int R = s * 32 + mt * 16 + (lm & 1) * 8 + lr;
            ldm_x4(ah[mi], &Hs[0][R][kt * 16 + (lm >> 1) * 8]);
            ldm_x4(al[mi], &Hs[1][R][kt * 16 + (lm >> 1) * 8]);
        }
#pragma unroll
        for (int nj = 0; nj < 2; nj++) {
            unsigned bh[2], bl[2];
            bfrag_pk(wo2h, wo2l, n0 + nj * 8 + g, kt, t, bh, bl);
#pragma unroll
            for (int mi = 0; mi < 4; mi++)
                mma3(d[mi][nj], ah[mi], al[mi], bh, bl);
        }
    }

    if (WRITE_ZS) __syncthreads();   // all Hs reads done before plane reuse

    // ---- epi2: +bo2 + residual -> out (and Xs planes if fusing zs) ----
#pragma unroll
    for (int mi = 0; mi < 4; mi++)
#pragma unroll
        for (int nj = 0; nj < 2; nj++) {
            int s = mi >> 1, mt = mi & 1;
            int r = mt * 16 + g;
            int R = s * 32 + r;
            int k = n0 + nj * 8 + 2 * t;
            long bb4 = (long)(b0 + s) * 4096;
            float2 bb = *(const float2*)&bo2[k];
            long base0 = FIRST ? (long)(r * 128 + k) : bb4 + r * 128 + k;
            long base1 = FIRST ? (long)((r + 8) * 128 + k) : bb4 + (r + 8) * 128 + k;
            float2 r0 = *(const float2*)&res[base0];
            float2 r1 = *(const float2*)&res[base1];
            float v0 = d[mi][nj][0] + bb.x + r0.x;
            float v1 = d[mi][nj][1] + bb.y + r0.y;
            float v2 = d[mi][nj][2] + bb.x + r1.x;
            float v3 = d[mi][nj][3] + bb.y + r1.y;
            *(float2*)&out[bb4 + r * 128 + k] = make_float2(v0, v1);
            *(float2*)&out[bb4 + (r + 8) * 128 + k] = make_float2(v2, v3);
            if (WRITE_ZS) {
                unsigned hi, lo;
                split2(v0, v1, hi, lo);
                *(unsigned*)&Hs[0][R][k] = hi;
                *(unsigned*)&Hs[1][R][k] = lo;
                split2(v2, v3, hi, lo);
                *(unsigned*)&Hs[0][R + 8][k] = hi;
                *(unsigned*)&Hs[1][R + 8][k] = lo;
            }
        }

    if (WRITE_ZS) {
        __syncthreads();

        // ---- GEMM3: xs_new @ Win_next^T -> zs rows 0..31 (both samples) ----
        float e[4][2][4];
#pragma unroll
        for (int mi = 0; mi < 4; mi++)
#pragma unroll
            for (int nj = 0; nj < 2; nj++)
#pragma unroll
                for (int q = 0; q < 4; q++) e[mi][nj][q] = 0.f;

#pragma unroll
        for (int kt = 0; kt < 8; kt++) {
            unsigned ah[4][4], al[4][4];
#pragma unroll
            for (int mi = 0; mi < 4; mi++) {
                int s = mi >> 1, mt = mi & 1;
                int R = s * 32 + mt * 16 + (lm & 1) * 8 + lr;
                ldm_x4(ah[mi], &Hs[0][R][kt * 16 + (lm >> 1) * 8]);
                ldm_x4(al[mi], &Hs[1][R][kt * 16 + (lm >> 1) * 8]);
            }
#pragma unroll
            for (int nj = 0; nj < 2; nj++) {
                unsigned bh[2], bl[2];
                bfrag_pk(winh, winl, n0 + nj * 8 + g, kt, t, bh, bl);
#pragma unroll
                for (int mi = 0; mi < 4; mi++)
                    mma3(e[mi][nj], ah[mi], al[mi], bh, bl);
            }
        }

#pragma unroll
        for (int mi = 0; mi < 4; mi++)
#pragma unroll
            for (int nj = 0; nj < 2; nj++) {
                int s = mi >> 1, mt = mi & 1;
                int r = mt * 16 + g;
                int k = n0 + nj * 8 + 2 * t;
                long zb = (long)(b0 + s) * NALL;
                *(float2*)&zs[(zb + r) * 128 + k] =
                    make_float2(e[mi][nj][0], e[mi][nj][1]);
                *(float2*)&zs[(zb + r + 8) * 128 + k] =
                    make_float2(e[mi][nj][2], e[mi][nj][3]);
            }
    }
}

// ---------------------------------------------------------------------------
// Pair conv: term-split accumulator chains; zs[b] staged to dynamic smem.
// ---------------------------------------------------------------------------
#define ZS_SMEM_WORDS (36 * 132)
#define ZS_SMEM_BYTES (ZS_SMEM_WORDS * 4)

__global__ __launch_bounds__(288, 2) void pairconv_mma_kernel(
    const float* __restrict__ dists,   // (B,32,36,32) fp32
    const unsigned* __restrict__ w1h, const unsigned* __restrict__ w1l,
    const float* __restrict__ b1g,
    const unsigned* __restrict__ w2h, const unsigned* __restrict__ w2l,
    const float* __restrict__ b2g,
    const float* __restrict__ zs,
    unsigned* __restrict__ zh, unsigned* __restrict__ zl)
{
    __shared__ unsigned short W1s[2][64][40];
    __shared__ unsigned short W2s[2][128][72];
    __shared__ float z_s[8][128];
    extern __shared__ float zs_s[];   // [36][132]

    int tid = threadIdx.x;
    int b = blockIdx.x >> 2;
    int e0g = (blockIdx.x & 3) * 8;
    int wid = tid >> 5, lane = tid & 31;
    int g = lane >> 2, t = lane & 3;
    int lr = lane & 7, lm = lane >> 3;

    // stage pre-split weight planes
    for (int idx = tid; idx < 64 * 16; idx += 288) {
        int n = idx >> 4, kp = idx & 15;
        *(unsigned*)&W1s[0][n][2 * kp] = w1h[idx];
        *(unsigned*)&W1s[1][n][2 * kp] = w1l[idx];
    }
    for (int idx = tid; idx < 128 * 32; idx += 288) {
        int n = idx >> 5, kp = idx & 31;
        *(unsigned*)&W2s[0][n][2 * kp] = w2h[idx];
        *(unsigned*)&W2s[1][n][2 * kp] = w2l[idx];
    }
    // stage zs[b] into padded smem
    {
        const float* zrow = zs + b * (36 * 128);
        for (int idx = tid; idx < 1152; idx += 288) {
            int j = idx >> 5, k4 = idx & 31;
            float4 v = *(const float4*)&zrow[j * 128 + k4 * 4];
            *(float4*)&zs_s[j * 132 + k4 * 4] = v;
        }
    }
    for (int idx = tid; idx < 1024; idx += 288) ((float*)z_s)[idx] = 0.f;
    __syncthreads();

    const float* drow = dists + ((long)(b * 32 + e0g) * 36) * 32;

    int e_lo = (wid * 32) / 36;
    int e_hi = (wid * 32 + 31) / 36;

    unsigned a2h[2][4][4], a2l[2][4][4];
    int ja_[2], jb_[2];
    bool skip0_[2], skip1_[2];
    bool hi0_[2], hi1_[2];

#pragma unroll
    for (int i = 0; i < 2; i++) {
        int mb = wid * 32 + i * 16;
        int r0 = mb + g, r1 = r0 + 8;
        int ea = r0 / 36, ja = r0 - 36 * ea;
        int eb = r1 / 36, jb = r1 - 36 * eb;
        ja_[i] = ja; jb_[i] = jb;
        skip0_[i] = (ja == e0g + ea);
        skip1_[i] = (jb == e0g + eb);
        hi0_[i] = (ea != e_lo);
        hi1_[i] = (eb != e_lo);

        // A-fragments of db (fp32 load + split)
        unsigned ah[2][4], al[2][4];
#pragma unroll
        for (int kt = 0; kt < 2; kt++) {
            int col = 16 * kt + 2 * t;
            float2 v00 = *(const float2*)&drow[(ea * 36 + ja) * 32 + col];
            float2 v10 = *(const float2*)&drow[(eb * 36 + jb) * 32 + col];
            float2 v01 = *(const float2*)&drow[(ea * 36 + ja) * 32 + col + 8];
            float2 v11 = *(const float2*)&drow[(eb * 36 + jb) * 32 + col + 8];
            split2(v00.x, v00.y, ah[kt][0], al[kt][0]);
            split2(v10.x, v10.y, ah[kt][1], al[kt][1]);
            split2(v01.x, v01.y, ah[kt][2], al[kt][2]);
            split2(v11.x, v11.y, ah[kt][3], al[kt][3]);
        }

        // GEMM1: term-split, 3 chains of 2
        float c1[8][4];
#pragma unroll
        for (int nt = 0; nt < 8; nt++) {
            unsigned bh[4], bl[4];
            ldm_x4(bh, &W1s[0][nt * 8 + lr][8 * lm]);
            ldm_x4(bl, &W1s[1][nt * 8 + lr][8 * lm]);
            float cP[4] = {0.f, 0.f, 0.f, 0.f};
            float cQ[4] = {0.f, 0.f, 0.f, 0.f};
            float cR[4] = {0.f, 0.f, 0.f, 0.f};
            mma3t(cP, cQ, cR, ah[0], al[0], &bh[0], &bl[0]);
            mma3t(cP, cQ, cR, ah[1], al[1], &bh[2], &bl[2]);
#pragma unroll
            for (int q = 0; q < 4; q++) c1[nt][q] = (cP[q] + cQ[q]) + cR[q];
        }

#pragma unroll
        for (int kt2 = 0; kt2 < 4; kt2++) {
            int n0 = 2 * kt2, n1 = n0 + 1;
            float2 bb0 = *(const float2*)&b1g[n0 * 8 + 2 * t];
            float2 bb1 = *(const float2*)&b1g[n1 * 8 + 2 * t];
            split2(sspf(c1[n0][0] + bb0.x), sspf(c1[n0][1] + bb0.y), a2h[i][kt2][0], a2l[i][kt2][0]);
            split2(sspf(c1[n0][2] + bb0.x), sspf(c1[n0][3] + bb0.y), a2h[i][kt2][1], a2l[i][kt2][1]);
            split2(sspf(c1[n1][0] + bb1.x), sspf(c1[n1][1] + bb1.y), a2h[i][kt2][2], a2l[i][kt2][2]);
            split2(sspf(c1[n1][2] + bb1.x), sspf(c1[n1][3] + bb1.y), a2h[i][kt2][3], a2l[i][kt2][3]);
        }
    }

#pragma unroll
    for (int half = 0; half < 2; half++) {
#pragma unroll
        for (int nt = 0; nt < 8; nt++) {
            int nn = half * 64 + nt * 8;
            int k0 = nn + 2 * t;

            unsigned h0[4], h1[4], l0[4], l1[4];
            ldm_x4(h0, &W2s[0][nn + lr][8 * lm]);
            ldm_x4(h1, &W2s[0][nn + lr][32 + 8 * lm]);
            ldm_x4(l0, &W2s[1][nn + lr][8 * lm]);
            ldm_x4(l1, &W2s[1][nn + lr][32 + 8 * lm]);
            float2 bb = *(const float2*)&b2g[k0];

            float acc0[2] = {0.f, 0.f};
            float acc1[2] = {0.f, 0.f};

#pragma unroll
            for (int i = 0; i < 2; i++) {
                float2 zj0 = skip0_[i] ? make_float2(0.f, 0.f)
                                       : *(const float2*)&zs_s[ja_[i] * 132 + k0];
                float2 zj1 = skip1_[i] ? make_float2(0.f, 0.f)
                                       : *(const float2*)&zs_s[jb_[i] * 132 + k0];

                // GEMM2: term-split, 3 chains of 4
                float cP[4] = {0.f, 0.f, 0.f, 0.f};
                float cQ[4] = {0.f, 0.f, 0.f, 0.f};
                float cR[4] = {0.f, 0.f, 0.f, 0.f};
                mma3t(cP, cQ, cR, a2h[i][0], a2l[i][0], &h0[0], &l0[0]);
                mma3t(cP, cQ, cR, a2h[i][1], a2l[i][1], &h0[2], &l0[2]);
                mma3t(cP, cQ, cR, a2h[i][2], a2l[i][2], &h1[0], &l1[0]);
                mma3t(cP, cQ, cR, a2h[i][3], a2l[i][3], &h1[2], &l1[2]);

                float p0 = ((cP[0] + cQ[0]) + cR[0] + bb.x) * zj0.x;
                float p1 = ((cP[1] + cQ[1]) + cR[1] + bb.y) * zj0.y;
                float p2 = ((cP[2] + cQ[2]) + cR[2] + bb.x) * zj1.x;
                float p3 = ((cP[3] + cQ[3]) + cR[3] + bb.y) * zj1.y;
                if (hi0_[i]) { acc1[0] += p0; acc1[1] += p1; }
                else         { acc0[0] += p0; acc0[1] += p1; }
                if (hi1_[i]) { acc1[0] += p2; acc1[1] += p3; }
                else         { acc0[0] += p2; acc0[1] += p3; }
            }

#pragma unroll
            for (int q = 0; q < 2; q++) {
                float v = acc0[q];
                v += __shfl_down_sync(0xffffffffu, v, 16);
                v += __shfl_down_sync(0xffffffffu, v, 8);
                v += __shfl_down_sync(0xffffffffu, v, 4);
                float w = acc1[q];
                w += __shfl_down_sync(0xffffffffu, w, 16);
                w += __shfl_down_sync(0xffffffffu, w, 8);
                w += __shfl_down_sync(0xffffffffu, w, 4);
                if (lane < 4) {
                    int k = nn + 2 * lane + q;
                    atomicAdd(&z_s[e_lo][k], v);
                    if (e_hi != e_lo) atomicAdd(&z_s[e_hi][k], w);
                }
            }
        }
    }

    __syncthreads();
    // write z as packed bf16 planes (fragment-ready perm layout, 64 words/row)
    for (int idx = tid; idx < 512; idx += 288) {
        int e = idx >> 6, w = idx & 63;
        int kt = w >> 3, i2 = w & 7, tt = i2 >> 1, h = i2 & 1;
        int c0 = kt * 16 + 2 * tt + 8 * h;
        unsigned hi, lo;
        split2(z_s[e][c0], z_s[e][c0 + 1], hi, lo);
        long off = (long)(b * 32 + e0g + e) * 64 + w;
        zh[off] = hi;
        zl[off] = lo;
    }
}

// ---------------------------------------------------------------------------
// launch
// ---------------------------------------------------------------------------
extern "C" void kernel_launch(void* const* d_in, const int* in_sizes, int n_in,
                              void* d_out, int out_size)
{
    const float* dists = (const float*)d_in[0];
    const float* emb_e = (const float*)d_in[1];
    const float* emb_n = (const float*)d_in[2];
    const float* w1    = (const float*)d_in[3];
    const float* b1    = (const float*)d_in[4];
    const float* w2    = (const float*)d_in[5];
    const float* b2    = (const float*)d_in[6];
    const float* win   = (const float*)d_in[7];
    const float* wo1   = (const float*)d_in[8];
    const float* bo1   = (const float*)d_in[9];
    const float* wo2   = (const float*)d_in[10];
    const float* bo2   = (const float*)d_in[11];
    float* out = (float*)d_out;

    float *xs, *zsv;
    unsigned *zh, *zl, *eh, *el;
    unsigned *winh, *winl, *wo1h, *wo1l, *wo2h, *wo2l;
    unsigned *w1h, *w1l, *w2h, *w2l;
    cudaGetSymbolAddress((void**)&xs,   g_xs);
    cudaGetSymbolAddress((void**)&zsv,  g_zs);
    cudaGetSymbolAddress((void**)&zh,   g_zh);
    cudaGetSymbolAddress((void**)&zl,   g_zl);
    cudaGetSymbolAddress((void**)&eh,   g_eh);
    cudaGetSymbolAddress((void**)&el,   g_el);
    cudaGetSymbolAddress((void**)&winh, g_winh);
    cudaGetSymbolAddress((void**)&winl, g_winl);
    cudaGetSymbolAddress((void**)&wo1h, g_wo1h);
    cudaGetSymbolAddress((void**)&wo1l, g_wo1l);
    cudaGetSymbolAddress((void**)&wo2h, g_wo2h);
    cudaGetSymbolAddress((void**)&wo2l, g_wo2l);
    cudaGetSymbolAddress((void**)&w1h,  g_w1h);
    cudaGetSymbolAddress((void**)&w1l,  g_w1l);
    cudaGetSymbolAddress((void**)&w2h,  g_w2h);
    cudaGetSymbolAddress((void**)&w2l,  g_w2l);

    // ---- single fused prep launch ----
    pack_all_kernel<<<(PACK_ALL_TOTAL + 255) / 256, 256>>>(
        w1, w2, emb_e, win, wo1, wo2, emb_n,
        w1h, w1l, w2h, w2l, eh, el,
        winh, winl, wo1h, wo1l, wo2h, wo2l, zsv);

    // t=0 zs linear (xs == emb broadcast)
    zslin_first_kernel<<<BATCH, 256>>>(eh, el, winh, winl, zsv);

    // t = 0
    pairconv_mma_kernel<<<BATCH * 4, 288, ZS_SMEM_BYTES>>>(
        dists, w1h, w1l, b1, w2h, w2l, b2, zsv, zh, zl);
    outmlp_mma_kernel<true, true><<<BATCH / 2, 256>>>(
        zh, zl, wo1h, wo1l, bo1, wo2h, wo2l, bo2, emb_e, xs,
        winh + 1 * 8192, winl + 1 * 8192, zsv);

    // t = 1
    pairconv_mma_kernel<<<BATCH * 4, 288, ZS_SMEM_BYTES>>>(
        dists, w1h + 1024, w1l + 1024, b1 + HIDK,
        w2h + 4096, w2l + 4096, b2 + KDIM, zsv, zh, zl);
    outmlp_mma_kernel<false, true><<<BATCH / 2, 256>>>(
        zh, zl, wo1h + 8192, wo1l + 8192, bo1 + HIDO,
        wo2h + 8192, wo2l + 8192, bo2 + EDIM, xs, xs,
        winh + 2 * 8192, winl + 2 * 8192, zsv);

    // t = 2: final, write d_out
    pairconv_mma_kernel<<<BATCH * 4, 288, ZS_SMEM_BYTES>>>(
        dists, w1h + 2048, w1l + 2048, b1 + 2 * HIDK,
        w2h + 8192, w2l + 8192, b2 + 2 * KDIM, zsv, zh, zl);
    outmlp_mma_kernel<false, false><<<BATCH / 2, 256>>>(
        zh, zl, wo1h + 2 * 8192, wo1l + 2 * 8192, bo1 + 2 * HIDO,
        wo2h + 2 * 8192, wo2l + 2 * 8192, bo2 + 2 * EDIM, xs, out,
        nullptr, nullptr, nullptr);
}

// round 15
// speedup vs baseline: 1.0466x; 1.0466x over previous
#include <cuda_runtime.h>
#include <cstdint>

#define BATCH  512
#define NELEC  32
#define NALL   36
#define NNUC   4
#define BASIS  32
#define KDIM   128
#define EDIM   128
#define HIDK   64
#define HIDO   128

// ---------------- scratch (device globals; no runtime allocation) ----------
__device__ float g_xs[BATCH * NELEC * EDIM];          // fp32 residual stream
__device__ float g_zs[BATCH * NALL * KDIM];           // fp32 zs (zj reads)
// packed bf16x2 plane buffers (hi/lo)
__device__ __align__(16) unsigned g_zh[BATCH * NELEC * 64];
__device__ __align__(16) unsigned g_zl[BATCH * NELEC * 64];
__device__ __align__(16) unsigned g_eh[32 * 64];
__device__ __align__(16) unsigned g_el[32 * 64];
__device__ __align__(16) unsigned g_winh[3 * 128 * 64];
__device__ __align__(16) unsigned g_winl[3 * 128 * 64];
__device__ __align__(16) unsigned g_wo1h[3 * 128 * 64];
__device__ __align__(16) unsigned g_wo1l[3 * 128 * 64];
__device__ __align__(16) unsigned g_wo2h[3 * 128 * 64];
__device__ __align__(16) unsigned g_wo2l[3 * 128 * 64];
__device__ __align__(16) unsigned g_w1h[3 * 64 * 16];   // plain layout
__device__ __align__(16) unsigned g_w1l[3 * 64 * 16];
__device__ __align__(16) unsigned g_w2h[3 * 128 * 32];  // plain layout
__device__ __align__(16) unsigned g_w2l[3 * 128 * 32];

__device__ __forceinline__ float sspf(float x) {
    float e = __expf(-fabsf(x));
    float l = __logf(1.0f + e);
    return fmaxf(x, 0.0f) + l - 0.69314718055994530942f;
}

// ---------------- bf16 MMA helpers ----------------
__device__ __forceinline__ void mma_bf16(float* c, const unsigned* a, const unsigned* b) {
    asm volatile("mma.sync.aligned.m16n8k16.row.col.f32.bf16.bf16.f32 "
        "{%0,%1,%2,%3}, {%4,%5,%6,%7}, {%8,%9}, {%0,%1,%2,%3};"
        : "+f"(c[0]), "+f"(c[1]), "+f"(c[2]), "+f"(c[3])
        : "r"(a[0]), "r"(a[1]), "r"(a[2]), "r"(a[3]), "r"(b[0]), "r"(b[1]));
}
__device__ __forceinline__ void mma3(float* c, const unsigned* ah, const unsigned* al,
                                     const unsigned* bh, const unsigned* bl) {
    mma_bf16(c, ah, bh);
    mma_bf16(c, al, bh);
    mma_bf16(c, ah, bl);
}
__device__ __forceinline__ unsigned pack_bf16(float f0, float f1) {
    unsigned r;
    asm("cvt.rn.bf16x2.f32 %0, %1, %2;" : "=r"(r) : "f"(f1), "f"(f0));
    return r;
}
__device__ __forceinline__ void split2(float f0, float f1, unsigned &hi, unsigned &lo) {
    hi = pack_bf16(f0, f1);
    float h0 = __uint_as_float(hi << 16);
    float h1 = __uint_as_float(hi & 0xFFFF0000u);
    lo = pack_bf16(f0 - h0, f1 - h1);
}
__device__ __forceinline__ void ldm_x4(unsigned* r, const void* p) {
    unsigned a = (unsigned)__cvta_generic_to_shared(p);
    asm volatile("ldmatrix.sync.aligned.m8n8.x4.shared.b16 {%0,%1,%2,%3}, [%4];"
                 : "=r"(r[0]), "=r"(r[1]), "=r"(r[2]), "=r"(r[3]) : "r"(a));
}

// packed-plane B fragment
__device__ __forceinline__ void bfrag_pk(const unsigned* Wh, const unsigned* Wl,
                                         int n, int kt, int t,
                                         unsigned* bh, unsigned* bl) {
    uint2 uh = *(const uint2*)&Wh[n * 64 + kt * 8 + 2 * t];
    uint2 ul = *(const uint2*)&Wl[n * 64 + kt * 8 + 2 * t];
    bh[0] = uh.x; bh[1] = uh.y;
    bl[0] = ul.x; bl[1] = ul.y;
}
// packed-plane A fragment (ldw = words/row)
__device__ __forceinline__ void afrag_pk(const unsigned* Ah, const unsigned* Al,
                                         int r, int kt, int t, int ldw,
                                         unsigned* ah, unsigned* al) {
    uint2 uh0 = *(const uint2*)&Ah[r * ldw + kt * 8 + 2 * t];
    uint2 uh1 = *(const uint2*)&Ah[(r + 8) * ldw + kt * 8 + 2 * t];
    uint2 ul0 = *(const uint2*)&Al[r * ldw + kt * 8 + 2 * t];
    uint2 ul1 = *(const uint2*)&Al[(r + 8) * ldw + kt * 8 + 2 * t];
    ah[0] = uh0.x; ah[2] = uh0.y; ah[1] = uh1.x; ah[3] = uh1.y;
    al[0] = ul0.x; al[2] = ul0.y; al[1] = ul1.x; al[3] = ul1.y;
}

// ---------------------------------------------------------------------------
// single fused prep kernel
// ---------------------------------------------------------------------------
__device__ __forceinline__ void pack_plain_one(const float* src, unsigned* dh,
                                               unsigned* dl, int idx) {
    unsigned hi, lo;
    split2(src[2 * idx], src[2 * idx + 1], hi, lo);
    dh[idx] = hi; dl[idx] = lo;
}
__device__ __forceinline__ void pack_perm_one(const float* src, unsigned* dh,
                                              unsigned* dl, int idx, int cwords) {
    int r = idx / cwords, w = idx - r * cwords;
    int kt = w >> 3, i = w & 7, t = i >> 1, h = i & 1;
    int c0 = kt * 16 + 2 * t + 8 * h;
    const float* row = src + (long)r * (cwords * 2);
    unsigned hi, lo;
    split2(row[c0], row[c0 + 1], hi, lo);
    dh[idx] = hi; dl[idx] = lo;
}

__global__ void pack_all_kernel(
    const float* __restrict__ w1, const float* __restrict__ w2,
    const float* __restrict__ emb_e,
    const float* __restrict__ win, const float* __restrict__ wo1,
    const float* __restrict__ wo2, const float* __restrict__ emb_n,
    unsigned* __restrict__ w1h, unsigned* __restrict__ w1l,
    unsigned* __restrict__ w2h, unsigned* __restrict__ w2l,
    unsigned* __restrict__ eh, unsigned* __restrict__ el,
    unsigned* __restrict__ winh, unsigned* __restrict__ winl,
    unsigned* __restrict__ wo1h, unsigned* __restrict__ wo1l,
    unsigned* __restrict__ wo2h, unsigned* __restrict__ wo2l,
    float* __restrict__ zs)
{
    int idx = blockIdx.x * blockDim.x + threadIdx.x;
    if (idx < 3072) { pack_plain_one(w1, w1h, w1l, idx); return; }
    idx -= 3072;
    if (idx < 12288) { pack_plain_one(w2, w2h, w2l, idx); return; }
    idx -= 12288;
    if (idx < 2048) { pack_perm_one(emb_e, eh, el, idx, 64); return; }
    idx -= 2048;
    if (idx < 24576) { pack_perm_one(win, winh, winl, idx, 64); return; }
    idx -= 24576;
    if (idx < 24576) { pack_perm_one(wo1, wo1h, wo1l, idx, 64); return; }
    idx -= 24576;
    if (idx < 24576) { pack_perm_one(wo2, wo2h, wo2l, idx, 64); return; }
    idx -= 24576;
    if (idx < BATCH * NNUC * KDIM) {
        int d = idx & 127;
        int m = (idx >> 7) & 3;
        int b = idx >> 9;
        zs[(b * NALL + NELEC + m) * KDIM + d] = emb_n[m * KDIM + d];
    }
}
#define PACK_ALL_TOTAL (3072 + 12288 + 2048 + 3 * 24576 + BATCH * NNUC * KDIM)

// ---------------------------------------------------------------------------
// zs linear for t=0 (unchanged — passing)
// ---------------------------------------------------------------------------
__global__ __launch_bounds__(256) void zslin_first_kernel(
    const unsigned* __restrict__ eh, const unsigned* __restrict__ el,
    const unsigned* __restrict__ wh, const unsigned* __restrict__ wl,
    float* __restrict__ zs)
{
    int b = blockIdx.x;
    int tid = threadIdx.x;
    int wid = tid >> 5, lane = tid & 31;
    int g = lane >> 2, t = lane & 3;
    int n0 = wid * 16;

    float c[2][2][4];
#pragma unroll
    for (int mi = 0; mi < 2; mi++)
#pragma unroll
        for (int nj = 0; nj < 2; nj++)
#pragma unroll
            for (int q = 0; q < 4; q++) c[mi][nj][q] = 0.f;

#pragma unroll
    for (int kt = 0; kt < 8; kt++) {
        unsigned ah[2][4], al[2][4];
#pragma unroll
        for (int mi = 0; mi < 2; mi++)
            afrag_pk(eh, el, mi * 16 + g, kt, t, 64, ah[mi], al[mi]);
#pragma unroll
        for (int nj = 0; nj < 2; nj++) {
            unsigned bh[2], bl[2];
            bfrag_pk(wh, wl, n0 + nj * 8 + g, kt, t, bh, bl);
#pragma unroll
            for (int mi = 0; mi < 2; mi++)
                mma3(c[mi][nj], ah[mi], al[mi], bh, bl);
        }
    }
#pragma unroll
    for (int mi = 0; mi < 2; mi++)
#pragma unroll
        for (int nj = 0; nj < 2; nj++) {
            int r = mi * 16 + g;
            int k = n0 + nj * 8 + 2 * t;
            *(float2*)&zs[(b * NALL + r) * 128 + k] = make_float2(c[mi][nj][0], c[mi][nj][1]);
            *(float2*)&zs[(b * NALL + r + 8) * 128 + k] = make_float2(c[mi][nj][2], c[mi][nj][3]);
        }
}

// ---------------------------------------------------------------------------
// Fused out-MLP: 2 batch samples per CTA (grid = BATCH/2). (R14 — verified win)
// ---------------------------------------------------------------------------
template <bool FIRST, bool WRITE_ZS>
__global__ __launch_bounds__(256) void outmlp_mma_kernel(
    const unsigned* __restrict__ zh, const unsigned* __restrict__ zl,
    const unsigned* __restrict__ wo1h, const unsigned* __restrict__ wo1l,
    const float* __restrict__ bo1,
    const unsigned* __restrict__ wo2h, const unsigned* __restrict__ wo2l,
    const float* __restrict__ bo2,
    const float* __restrict__ res, float* __restrict__ out,
    const unsigned* __restrict__ winh, const unsigned* __restrict__ winl,
    float* __restrict__ zs)
{
    __shared__ unsigned short Hs[2][64][136];

    int b0 = blockIdx.x * 2;
    int tid = threadIdx.x;
    int wid = tid >> 5, lane = tid & 31;
    int g = lane >> 2, t = lane & 3;
    int lr = lane & 7, lm = lane >> 3;
    int n0 = wid * 16;

    // ---- GEMM1: z @ Wo1^T (both samples) ----
    float c[4][2][4];
#pragma unroll
    for (int mi = 0; mi < 4; mi++)
#pragma unroll
        for (int nj = 0; nj < 2; nj++)
#pragma unroll
            for (int q = 0; q < 4; q++) c[mi][nj][q] = 0.f;

#pragma unroll
    for (int kt = 0; kt < 8; kt++) {
        unsigned ah[4][4], al[4][4];
#pragma unroll
        for (int mi = 0; mi < 4; mi++) {
            int s = mi >> 1, mt = mi & 1;
            afrag_pk(zh + (long)(b0 + s) * 2048, zl + (long)(b0 + s) * 2048,
                     mt * 16 + g, kt, t, 64, ah[mi], al[mi]);
        }
#pragma unroll
        for (int nj = 0; nj < 2; nj++) {
            unsigned bh[2], bl[2];
            bfrag_pk(wo1h, wo1l, n0 + nj * 8 + g, kt, t, bh, bl);
#pragma unroll
            for (int mi = 0; mi < 4; mi++)
                mma3(c[mi][nj], ah[mi], al[mi], bh, bl);
        }
    }

    // ---- epi1: +bo1, ssp, split -> Hs ----
#pragma unroll
    for (int mi = 0; mi < 4; mi++)
#pragma unroll
        for (int nj = 0; nj < 2; nj++) {
            int s = mi >> 1, mt = mi & 1;
            int R = s * 32 + mt * 16 + g;
            int k = n0 + nj * 8 + 2 * t;
            float2 bb = *(const float2*)&bo1[k];
            unsigned hi, lo;
            split2(sspf(c[mi][nj][0] + bb.x), sspf(c[mi][nj][1] + bb.y), hi, lo);
            *(unsigned*)&Hs[0][R][k] = hi;
            *(unsigned*)&Hs[1][R][k] = lo;
            split2(sspf(c[mi][nj][2] + bb.x), sspf(c[mi][nj][3] + bb.y), hi, lo);
            *(unsigned*)&Hs[0][R + 8][k] = hi;
            *(unsigned*)&Hs[1][R + 8][k] = lo;
        }
    __syncthreads();

    // ---- GEMM2: h @ Wo2^T ----
    float d[4][2][4];
#pragma unroll
    for (int mi = 0; mi < 4; mi++)
#pragma unroll
        for (int nj = 0; nj < 2; nj++)
#pragma unroll
            for (int q = 0; q < 4; q++) d[mi][nj][q] = 0.f;

#pragma unroll
    for (int kt = 0; kt < 8; kt++) {
        unsigned ah[4][4], al[4][4];
#pragma unroll
        for (int mi = 0; mi < 4; mi++) {
            int s = mi >> 1, mt = mi & 1;
            int R = s * 32 + mt * 16 + (lm & 1) * 8 + lr;
            ldm_x4(ah[mi], &Hs[0][R][kt * 16 + (lm >> 1) * 8]);
            ldm_x4(al[mi], &Hs[1][R][kt * 16 + (lm >> 1) * 8]);
        }
#pragma unroll
        for (int nj = 0; nj < 2; nj++) {
            unsigned bh[2], bl[2];
            bfrag_pk(wo2h, wo2l, n0 + nj * 8 + g, kt, t, bh, bl);
#pragma unroll
            for (int mi = 0; mi < 4; mi++)
                mma3(d[mi][nj], ah[mi], al[mi], bh, bl);
        }
    }

    if (WRITE_ZS) __syncthreads();   // all Hs reads done before plane reuse

    // ---- epi2: +bo2 + residual -> out (and Xs planes if fusing zs) ----
#pragma unroll
    for (int mi = 0; mi < 4; mi++)
#pragma unroll
        for (int nj = 0; nj < 2; nj++) {
            int s = mi >> 1, mt = mi & 1;
            int r = mt * 16 + g;
            int R = s * 32 + r;
            int k = n0 + nj * 8 + 2 * t;
            long bb4 = (long)(b0 + s) * 4096;
            float2 bb = *(const float2*)&bo2[k];
            long base0 = FIRST ? (long)(r * 128 + k) : bb4 + r * 128 + k;
            long base1 = FIRST ? (long)((r + 8) * 128 + k) : bb4 + (r + 8) * 128 + k;
            float2 r0 = *(const float2*)&res[base0];
            float2 r1 = *(const float2*)&res[base1];
            float v0 = d[mi][nj][0] + bb.x + r0.x;
            float v1 = d[mi][nj][1] + bb.y + r0.y;
            float v2 = d[mi][nj][2] + bb.x + r1.x;
            float v3 = d[mi][nj][3] + bb.y + r1.y;
            *(float2*)&out[bb4 + r * 128 + k] = make_float2(v0, v1);
            *(float2*)&out[bb4 + (r + 8) * 128 + k] = make_float2(v2, v3);
            if (WRITE_ZS) {
                unsigned hi, lo;
                split2(v0, v1, hi, lo);
                *(unsigned*)&Hs[0][R][k] = hi;
                *(unsigned*)&Hs[1][R][k] = lo;
                split2(v2, v3, hi, lo);
                *(unsigned*)&Hs[0][R + 8][k] = hi;
                *(unsigned*)&Hs[1][R + 8][k] = lo;
            }
        }

    if (WRITE_ZS) {
        __syncthreads();

        // ---- GEMM3: xs_new @ Win_next^T -> zs rows 0..31 (both samples) ----
        float e[4][2][4];
#pragma unroll
        for (int mi = 0; mi < 4; mi++)
#pragma unroll
            for (int nj = 0; nj < 2; nj++)
#pragma unroll
                for (int q = 0; q < 4; q++) e[mi][nj][q] = 0.f;

#pragma unroll
        for (int kt = 0; kt < 8; kt++) {
            unsigned ah[4][4], al[4][4];
#pragma unroll
            for (int mi = 0; mi < 4; mi++) {
                int s = mi >> 1, mt = mi & 1;
                int R = s * 32 + mt * 16 + (lm & 1) * 8 + lr;
                ldm_x4(ah[mi], &Hs[0][R][kt * 16 + (lm >> 1) * 8]);
                ldm_x4(al[mi], &Hs[1][R][kt * 16 + (lm >> 1) * 8]);
            }
#pragma unroll
            for (int nj = 0; nj < 2; nj++) {
                unsigned bh[2], bl[2];
                bfrag_pk(winh, winl, n0 + nj * 8 + g, kt, t, bh, bl);
#pragma unroll
                for (int mi = 0; mi < 4; mi++)
                    mma3(e[mi][nj], ah[mi], al[mi], bh, bl);
            }
        }

#pragma unroll
        for (int mi = 0; mi < 4; mi++)
#pragma unroll
            for (int nj = 0; nj < 2; nj++) {
                int s = mi >> 1, mt = mi & 1;
                int r = mt * 16 + g;
                int k = n0 + nj * 8 + 2 * t;
                long zb = (long)(b0 + s) * NALL;
                *(float2*)&zs[(zb + r) * 128 + k] =
                    make_float2(e[mi][nj][0], e[mi][nj][1]);
                *(float2*)&zs[(zb + r + 8) * 128 + k] =
                    make_float2(e[mi][nj][2], e[mi][nj][3]);
            }
    }
}

// ---------------------------------------------------------------------------
// Pair conv (R13 version verbatim — verified ~195us/call): mma3 cA/cB split;
// zs[b] staged to dynamic smem; packed z output.
// ---------------------------------------------------------------------------
#define ZS_SMEM_WORDS (36 * 132)
#define ZS_SMEM_BYTES (ZS_SMEM_WORDS * 4)

__global__ __launch_bounds__(288, 2) void pairconv_mma_kernel(
    const float* __restrict__ dists,   // (B,32,36,32) fp32
    const unsigned* __restrict__ w1h, const unsigned* __restrict__ w1l,
    const float* __restrict__ b1g,
    const unsigned* __restrict__ w2h, const unsigned* __restrict__ w2l,
    const float* __restrict__ b2g,
    const float* __restrict__ zs,
    unsigned* __restrict__ zh, unsigned* __restrict__ zl)
{
    __shared__ unsigned short W1s[2][64][40];
    __shared__ unsigned short W2s[2][128][72];
    __shared__ float z_s[8][128];
    extern __shared__ float zs_s[];   // [36][132]

    int tid = threadIdx.x;
    int b = blockIdx.x >> 2;
    int e0g = (blockIdx.x & 3) * 8;
    int wid = tid >> 5, lane = tid & 31;
    int g = lane >> 2, t = lane & 3;
    int lr = lane & 7, lm = lane >> 3;

    // stage pre-split weight planes
    for (int idx = tid; idx < 64 * 16; idx += 288) {
        int n = idx >> 4, kp = idx & 15;
        *(unsigned*)&W1s[0][n][2 * kp] = w1h[idx];
        *(unsigned*)&W1s[1][n][2 * kp] = w1l[idx];
    }
    for (int idx = tid; idx < 128 * 32; idx += 288) {
        int n = idx >> 5, kp = idx & 31;
        *(unsigned*)&W2s[0][n][2 * kp] = w2h[idx];
        *(unsigned*)&W2s[1][n][2 * kp] = w2l[idx];
    }
    // stage zs[b] into padded smem
    {
        const float* zrow = zs + b * (36 * 128);
        for (int idx = tid; idx < 1152; idx += 288) {
            int j = idx >> 5, k4 = idx & 31;
            float4 v = *(const float4*)&zrow[j * 128 + k4 * 4];
            *(float4*)&zs_s[j * 132 + k4 * 4] = v;
        }
    }
    for (int idx = tid; idx < 1024; idx += 288) ((float*)z_s)[idx] = 0.f;
    __syncthreads();

    const float* drow = dists + ((long)(b * 32 + e0g) * 36) * 32;

    int e_lo = (wid * 32) / 36;
    int e_hi = (wid * 32 + 31) / 36;

    unsigned a2h[2][4][4], a2l[2][4][4];
    int ja_[2], jb_[2];
    bool skip0_[2], skip1_[2];
    bool hi0_[2], hi1_[2];

#pragma unroll
    for (int i = 0; i < 2; i++) {
        int mb = wid * 32 + i * 16;
        int r0 = mb + g, r1 = r0 + 8;
        int ea = r0 / 36, ja = r0 - 36 * ea;
        int eb = r1 / 36, jb = r1 - 36 * eb;
        ja_[i] = ja; jb_[i] = jb;
        skip0_[i] = (ja == e0g + ea);
        skip1_[i] = (jb == e0g + eb);
        hi0_[i] = (ea != e_lo);
        hi1_[i] = (eb != e_lo);

        // A-fragments of db (fp32 load + split)
        unsigned ah[2][4], al[2][4];
#pragma unroll
        for (int kt = 0; kt < 2; kt++) {
            int col = 16 * kt + 2 * t;
            float2 v00 = *(const float2*)&drow[(ea * 36 + ja) * 32 + col];
            float2 v10 = *(const float2*)&drow[(eb * 36 + jb) * 32 + col];
            float2 v01 = *(const float2*)&drow[(ea * 36 + ja) * 32 + col + 8];
            float2 v11 = *(const float2*)&drow[(eb * 36 + jb) * 32 + col + 8];
            split2(v00.x, v00.y, ah[kt][0], al[kt][0]);
            split2(v10.x, v10.y, ah[kt][1], al[kt][1]);
            split2(v01.x, v01.y, ah[kt][2], al[kt][2]);
            split2(v11.x, v11.y, ah[kt][3], al[kt][3]);
        }

        float c1[8][4];
#pragma unroll
        for (int nt = 0; nt < 8; nt++) {
            unsigned bh[4], bl[4];
            ldm_x4(bh, &W1s[0][nt * 8 + lr][8 * lm]);
            ldm_x4(bl, &W1s[1][nt * 8 + lr][8 * lm]);
            float cA[4] = {0.f, 0.f, 0.f, 0.f};
            float cB[4] = {0.f, 0.f, 0.f, 0.f};
            mma3(cA, ah[0], al[0], &bh[0], &bl[0]);
            mma3(cB, ah[1], al[1], &bh[2], &bl[2]);
#pragma unroll
            for (int q = 0; q < 4; q++) c1[nt][q] = cA[q] + cB[q];
        }

#pragma unroll
        for (int kt2 = 0; kt2 < 4; kt2++) {
            int n0 = 2 * kt2, n1 = n0 + 1;
            float2 bb0 = *(const float2*)&b1g[n0 * 8 + 2 * t];
            float2 bb1 = *(const float2*)&b1g[n1 * 8 + 2 * t];
            split2(sspf(c1[n0][0] + bb0.x), sspf(c1[n0][1] + bb0.y), a2h[i][kt2][0], a2l[i][kt2][0]);
            split2(sspf(c1[n0][2] + bb0.x), sspf(c1[n0][3] + bb0.y), a2h[i][kt2][1], a2l[i][kt2][1]);
            split2(sspf(c1[n1][0] + bb1.x), sspf(c1[n1][1] + bb1.y), a2h[i][kt2][2], a2l[i][kt2][2]);
            split2(sspf(c1[n1][2] + bb1.x), sspf(c1[n1][3] + bb1.y), a2h[i][kt2][3], a2l[i][kt2][3]);
        }
    }

#pragma unroll
    for (int half = 0; half < 2; half++) {
#pragma unroll
        for (int nt = 0; nt < 8; nt++) {
            int nn = half * 64 + nt * 8;
            int k0 = nn + 2 * t;

            unsigned h0[4], h1[4], l0[4], l1[4];
            ldm_x4(h0, &W2s[0][nn + lr][8 * lm]);
            ldm_x4(h1, &W2s[0][nn + lr][32 + 8 * lm]);
            ldm_x4(l0, &W2s[1][nn + lr][8 * lm]);
            ldm_x4(l1, &W2s[1][nn + lr][32 + 8 * lm]);
            float2 bb = *(const float2*)&b2g[k0];

            float acc0[2] = {0.f, 0.f};
            float acc1[2] = {0.f, 0.f};

#pragma unroll
            for (int i = 0; i < 2; i++) {
                float2 zj0 = skip0_[i] ? make_float2(0.f, 0.f)
                                       : *(const float2*)&zs_s[ja_[i] * 132 + k0];
                float2 zj1 = skip1_[i] ? make_float2(0.f, 0.f)
                                       : *(const float2*)&zs_s[jb_[i] * 132 + k0];

                float cA[4] = {0.f, 0.f, 0.f, 0.f};
                float cB[4] = {0.f, 0.f, 0.f, 0.f};
                mma3(cA, a2h[i][0], a2l[i][0], &h0[0], &l0[0]);
                mma3(cA, a2h[i][1], a2l[i][1], &h0[2], &l0[2]);
                mma3(cB, a2h[i][2], a2l[i][2], &h1[0], &l1[0]);
                mma3(cB, a2h[i][3], a2l[i][3], &h1[2], &l1[2]);

                float p0 = (cA[0] + cB[0] + bb.x) * zj0.x;
                float p1 = (cA[1] + cB[1] + bb.y) * zj0.y;
                float p2 = (cA[2] + cB[2] + bb.x) * zj1.x;
                float p3 = (cA[3] + cB[3] + bb.y) * zj1.y;
                if (hi0_[i]) { acc1[0] += p0; acc1[1] += p1; }
                else         { acc0[0] += p0; acc0[1] += p1; }
                if (hi1_[i]) { acc1[0] += p2; acc1[1] += p3; }
                else         { acc0[0] += p2; acc0[1] += p3; }
            }

#pragma unroll
            for (int q = 0; q < 2; q++) {
                float v = acc0[q];
                v += __shfl_down_sync(0xffffffffu, v, 16);
                v += __shfl_down_sync(0xffffffffu, v, 8);
                v += __shfl_down_sync(0xffffffffu, v, 4);
                float w = acc1[q];
                w += __shfl_down_sync(0xffffffffu, w, 16);
                w += __shfl_down_sync(0xffffffffu, w, 8);
                w += __shfl_down_sync(0xffffffffu, w, 4);
                if (lane < 4) {
                    int k = nn + 2 * lane + q;
                    atomicAdd(&z_s[e_lo][k], v);
                    if (e_hi != e_lo) atomicAdd(&z_s[e_hi][k], w);
                }
            }
        }
    }

    __syncthreads();
    // write z as packed bf16 planes (fragment-ready perm layout, 64 words/row)
    for (int idx = tid; idx < 512; idx += 288) {
        int e = idx >> 6, w = idx & 63;
        int kt = w >> 3, i2 = w & 7, tt = i2 >> 1, h = i2 & 1;
        int c0 = kt * 16 + 2 * tt + 8 * h;
        unsigned hi, lo;
        split2(z_s[e][c0], z_s[e][c0 + 1], hi, lo);
        long off = (long)(b * 32 + e0g + e) * 64 + w;
        zh[off] = hi;
        zl[off] = lo;
    }
}

// ---------------------------------------------------------------------------
// launch
// ---------------------------------------------------------------------------
extern "C" void kernel_launch(void* const* d_in, const int* in_sizes, int n_in,
                              void* d_out, int out_size)
{
    const float* dists = (const float*)d_in[0];
    const float* emb_e = (const float*)d_in[1];
    const float* emb_n = (const float*)d_in[2];
    const float* w1    = (const float*)d_in[3];
    const float* b1    = (const float*)d_in[4];
    const float* w2    = (const float*)d_in[5];
    const float* b2    = (const float*)d_in[6];
    const float* win   = (const float*)d_in[7];
    const float* wo1   = (const float*)d_in[8];
    const float* bo1   = (const float*)d_in[9];
    const float* wo2   = (const float*)d_in[10];
    const float* bo2   = (const float*)d_in[11];
    float* out = (float*)d_out;

    float *xs, *zsv;
    unsigned *zh, *zl, *eh, *el;
    unsigned *winh, *winl, *wo1h, *wo1l, *wo2h, *wo2l;
    unsigned *w1h, *w1l, *w2h, *w2l;
    cudaGetSymbolAddress((void**)&xs,   g_xs);
    cudaGetSymbolAddress((void**)&zsv,  g_zs);
    cudaGetSymbolAddress((void**)&zh,   g_zh);
    cudaGetSymbolAddress((void**)&zl,   g_zl);
    cudaGetSymbolAddress((void**)&eh,   g_eh);
    cudaGetSymbolAddress((void**)&el,   g_el);
    cudaGetSymbolAddress((void**)&winh, g_winh);
    cudaGetSymbolAddress((void**)&winl, g_winl);
    cudaGetSymbolAddress((void**)&wo1h, g_wo1h);
    cudaGetSymbolAddress((void**)&wo1l, g_wo1l);
    cudaGetSymbolAddress((void**)&wo2h, g_wo2h);
    cudaGetSymbolAddress((void**)&wo2l, g_wo2l);
    cudaGetSymbolAddress((void**)&w1h,  g_w1h);
    cudaGetSymbolAddress((void**)&w1l,  g_w1l);
    cudaGetSymbolAddress((void**)&w2h,  g_w2h);
    cudaGetSymbolAddress((void**)&w2l,  g_w2l);

    // ---- single fused prep launch ----
    pack_all_kernel<<<(PACK_ALL_TOTAL + 255) / 256, 256>>>(
        w1, w2, emb_e, win, wo1, wo2, emb_n,
        w1h, w1l, w2h, w2l, eh, el,
        winh, winl, wo1h, wo1l, wo2h, wo2l, zsv);

    // t=0 zs linear (xs == emb broadcast)
    zslin_first_kernel<<<BATCH, 256>>>(eh, el, winh, winl, zsv);

    // t = 0
    pairconv_mma_kernel<<<BATCH * 4, 288, ZS_SMEM_BYTES>>>(
        dists, w1h, w1l, b1, w2h, w2l, b2, zsv, zh, zl);
    outmlp_mma_kernel<true, true><<<BATCH / 2, 256>>>(
        zh, zl, wo1h, wo1l, bo1, wo2h, wo2l, bo2, emb_e, xs,
        winh + 1 * 8192, winl + 1 * 8192, zsv);

    // t = 1
    pairconv_mma_kernel<<<BATCH * 4, 288, ZS_SMEM_BYTES>>>(
        dists, w1h + 1024, w1l + 1024, b1 + HIDK,
        w2h + 4096, w2l + 4096, b2 + KDIM, zsv, zh, zl);
    outmlp_mma_kernel<false, true><<<BATCH / 2, 256>>>(
        zh, zl, wo1h + 8192, wo1l + 8192, bo1 + HIDO,
        wo2h + 8192, wo2l + 8192, bo2 + EDIM, xs, xs,
        winh + 2 * 8192, winl + 2 * 8192, zsv);

    // t = 2: final, write d_out
    pairconv_mma_kernel<<<BATCH * 4, 288, ZS_SMEM_BYTES>>>(
        dists, w1h + 2048, w1l + 2048, b1 + 2 * HIDK,
        w2h + 8192, w2l + 8192, b2 + 2 * KDIM, zsv, zh, zl);
    outmlp_mma_kernel<false, false><<<BATCH / 2, 256>>>(
        zh, zl, wo1h + 2 * 8192, wo1l + 2 * 8192, bo1 + 2 * HIDO,
        wo2h + 2 * 8192, wo2l + 2 * 8192, bo2 + 2 * EDIM, xs, out,
        nullptr, nullptr, nullptr);
}

// round 17
// speedup vs baseline: 1.0528x; 1.0059x over previous
#include <cuda_runtime.h>
#include <cstdint>

#define BATCH  512
#define NELEC  32
#define NALL   36
#define NNUC   4
#define BASIS  32
#define KDIM   128
#define EDIM   128
#define HIDK   64
#define HIDO   128

// ---------------- scratch (device globals; no runtime allocation) ----------
__device__ float g_xs[BATCH * NELEC * EDIM];          // fp32 residual stream
__device__ float g_zs[BATCH * NALL * KDIM];           // fp32 zs (zj reads)
// packed bf16x2 plane buffers (hi/lo)
__device__ __align__(16) unsigned g_zh[BATCH * NELEC * 64];
__device__ __align__(16) unsigned g_zl[BATCH * NELEC * 64];
__device__ __align__(16) unsigned g_eh[32 * 64];
__device__ __align__(16) unsigned g_el[32 * 64];
__device__ __align__(16) unsigned g_winh[3 * 128 * 64];
__device__ __align__(16) unsigned g_winl[3 * 128 * 64];
__device__ __align__(16) unsigned g_wo1h[3 * 128 * 64];
__device__ __align__(16) unsigned g_wo1l[3 * 128 * 64];
__device__ __align__(16) unsigned g_wo2h[3 * 128 * 64];
__device__ __align__(16) unsigned g_wo2l[3 * 128 * 64];
__device__ __align__(16) unsigned g_w1h[3 * 64 * 16];   // plain layout
__device__ __align__(16) unsigned g_w1l[3 * 64 * 16];
__device__ __align__(16) unsigned g_w2h[3 * 128 * 32];  // plain layout
__device__ __align__(16) unsigned g_w2l[3 * 128 * 32];

__device__ __forceinline__ float sspf(float x) {
    float e = __expf(-fabsf(x));
    float l = __logf(1.0f + e);
    return fmaxf(x, 0.0f) + l - 0.69314718055994530942f;
}

// ---------------- bf16 MMA helpers ----------------
__device__ __forceinline__ void mma_bf16(float* c, const unsigned* a, const unsigned* b) {
    asm volatile("mma.sync.aligned.m16n8k16.row.col.f32.bf16.bf16.f32 "
        "{%0,%1,%2,%3}, {%4,%5,%6,%7}, {%8,%9}, {%0,%1,%2,%3};"
        : "+f"(c[0]), "+f"(c[1]), "+f"(c[2]), "+f"(c[3])
        : "r"(a[0]), "r"(a[1]), "r"(a[2]), "r"(a[3]), "r"(b[0]), "r"(b[1]));
}
__device__ __forceinline__ void mma3(float* c, const unsigned* ah, const unsigned* al,
                                     const unsigned* bh, const unsigned* bl) {
    mma_bf16(c, ah, bh);
    mma_bf16(c, al, bh);
    mma_bf16(c, ah, bl);
}
__device__ __forceinline__ unsigned pack_bf16(float f0, float f1) {
    unsigned r;
    asm("cvt.rn.bf16x2.f32 %0, %1, %2;" : "=r"(r) : "f"(f1), "f"(f0));
    return r;
}
__device__ __forceinline__ void split2(float f0, float f1, unsigned &hi, unsigned &lo) {
    hi = pack_bf16(f0, f1);
    float h0 = __uint_as_float(hi << 16);
    float h1 = __uint_as_float(hi & 0xFFFF0000u);
    lo = pack_bf16(f0 - h0, f1 - h1);
}
__device__ __forceinline__ void ldm_x4(unsigned* r, const void* p) {
    unsigned a = (unsigned)__cvta_generic_to_shared(p);
    asm volatile("ldmatrix.sync.aligned.m8n8.x4.shared.b16 {%0,%1,%2,%3}, [%4];"
                 : "=r"(r[0]), "=r"(r[1]), "=r"(r[2]), "=r"(r[3]) : "r"(a));
}

// packed-plane B fragment
__device__ __forceinline__ void bfrag_pk(const unsigned* Wh, const unsigned* Wl,
                                         int n, int kt, int t,
                                         unsigned* bh, unsigned* bl) {
    uint2 uh = *(const uint2*)&Wh[n * 64 + kt * 8 + 2 * t];
    uint2 ul = *(const uint2*)&Wl[n * 64 + kt * 8 + 2 * t];
    bh[0] = uh.x; bh[1] = uh.y;
    bl[0] = ul.x; bl[1] = ul.y;
}
// packed-plane A fragment (ldw = words/row)
__device__ __forceinline__ void afrag_pk(const unsigned* Ah, const unsigned* Al,
                                         int r, int kt, int t, int ldw,
                                         unsigned* ah, unsigned* al) {
    uint2 uh0 = *(const uint2*)&Ah[r * ldw + kt * 8 + 2 * t];
    uint2 uh1 = *(const uint2*)&Ah[(r + 8) * ldw + kt * 8 + 2 * t];
    uint2 ul0 = *(const uint2*)&Al[r * ldw + kt * 8 + 2 * t];
    uint2 ul1 = *(const uint2*)&Al[(r + 8) * ldw + kt * 8 + 2 * t];
    ah[0] = uh0.x; ah[2] = uh0.y; ah[1] = uh1.x; ah[3] = uh1.y;
    al[0] = ul0.x; al[2] = ul0.y; al[1] = ul1.x; al[3] = ul1.y;
}

// ---------------------------------------------------------------------------
// single fused prep kernel
// ---------------------------------------------------------------------------
__device__ __forceinline__ void pack_plain_one(const float* src, unsigned* dh,
                                               unsigned* dl, int idx) {
    unsigned hi, lo;
    split2(src[2 * idx], src[2 * idx + 1], hi, lo);
    dh[idx] = hi; dl[idx] = lo;
}
__device__ __forceinline__ void pack_perm_one(const float* src, unsigned* dh,
                                              unsigned* dl, int idx, int cwords) {
    int r = idx / cwords, w = idx - r * cwords;
    int kt = w >> 3, i = w & 7, t = i >> 1, h = i & 1;
    int c0 = kt * 16 + 2 * t + 8 * h;
    const float* row = src + (long)r * (cwords * 2);
    unsigned hi, lo;
    split2(row[c0], row[c0 + 1], hi, lo);
    dh[idx] = hi; dl[idx] = lo;
}

__global__ void pack_all_kernel(
    const float* __restrict__ w1, const float* __restrict__ w2,
    const float* __restrict__ emb_e,
    const float* __restrict__ win, const float* __restrict__ wo1,
    const float* __restrict__ wo2, const float* __restrict__ emb_n,
    unsigned* __restrict__ w1h, unsigned* __restrict__ w1l,
    unsigned* __restrict__ w2h, unsigned* __restrict__ w2l,
    unsigned* __restrict__ eh, unsigned* __restrict__ el,
    unsigned* __restrict__ winh, unsigned* __restrict__ winl,
    unsigned* __restrict__ wo1h, unsigned* __restrict__ wo1l,
    unsigned* __restrict__ wo2h, unsigned* __restrict__ wo2l,
    float* __restrict__ zs)
{
    int idx = blockIdx.x * blockDim.x + threadIdx.x;
    if (idx < 3072) { pack_plain_one(w1, w1h, w1l, idx); return; }
    idx -= 3072;
    if (idx < 12288) { pack_plain_one(w2, w2h, w2l, idx); return; }
    idx -= 12288;
    if (idx < 2048) { pack_perm_one(emb_e, eh, el, idx, 64); return; }
    idx -= 2048;
    if (idx < 24576) { pack_perm_one(win, winh, winl, idx, 64); return; }
    idx -= 24576;
    if (idx < 24576) { pack_perm_one(wo1, wo1h, wo1l, idx, 64); return; }
    idx -= 24576;
    if (idx < 24576) { pack_perm_one(wo2, wo2h, wo2l, idx, 64); return; }
    idx -= 24576;
    if (idx < BATCH * NNUC * KDIM) {
        int d = idx & 127;
        int m = (idx >> 7) & 3;
        int b = idx >> 9;
        zs[(b * NALL + NELEC + m) * KDIM + d] = emb_n[m * KDIM + d];
    }
}
#define PACK_ALL_TOTAL (3072 + 12288 + 2048 + 3 * 24576 + BATCH * NNUC * KDIM)

// ---------------------------------------------------------------------------
// zs linear for t=0 (unchanged — passing)
// ---------------------------------------------------------------------------
__global__ __launch_bounds__(256) void zslin_first_kernel(
    const unsigned* __restrict__ eh, const unsigned* __restrict__ el,
    const unsigned* __restrict__ wh, const unsigned* __restrict__ wl,
    float* __restrict__ zs)
{
    int b = blockIdx.x;
    int tid = threadIdx.x;
    int wid = tid >> 5, lane = tid & 31;
    int g = lane >> 2, t = lane & 3;
    int n0 = wid * 16;

    float c[2][2][4];
#pragma unroll
    for (int mi = 0; mi < 2; mi++)
#pragma unroll
        for (int nj = 0; nj < 2; nj++)
#pragma unroll
            for (int q = 0; q < 4; q++) c[mi][nj][q] = 0.f;

#pragma unroll
    for (int kt = 0; kt < 8; kt++) {
        unsigned ah[2][4], al[2][4];
#pragma unroll
        for (int mi = 0; mi < 2; mi++)
            afrag_pk(eh, el, mi * 16 + g, kt, t, 64, ah[mi], al[mi]);
#pragma unroll
        for (int nj = 0; nj < 2; nj++) {
            unsigned bh[2], bl[2];
            bfrag_pk(wh, wl, n0 + nj * 8 + g, kt, t, bh, bl);
#pragma unroll
            for (int mi = 0; mi < 2; mi++)
                mma3(c[mi][nj], ah[mi], al[mi], bh, bl);
        }
    }
#pragma unroll
    for (int mi = 0; mi < 2; mi++)
#pragma unroll
        for (int nj = 0; nj < 2; nj++) {
            int r = mi * 16 + g;
            int k = n0 + nj * 8 + 2 * t;
            *(float2*)&zs[(b * NALL + r) * 128 + k] = make_float2(c[mi][nj][0], c[mi][nj][1]);
            *(float2*)&zs[(b * NALL + r + 8) * 128 + k] = make_float2(c[mi][nj][2], c[mi][nj][3]);
        }
}

// ---------------------------------------------------------------------------
// Fused out-MLP: 2 batch samples per CTA (R14 — verified win, unchanged)
// ---------------------------------------------------------------------------
template <bool FIRST, bool WRITE_ZS>
__global__ __launch_bounds__(256) void outmlp_mma_kernel(
    const unsigned* __restrict__ zh, const unsigned* __restrict__ zl,
    const unsigned* __restrict__ wo1h, const unsigned* __restrict__ wo1l,
    const float* __restrict__ bo1,
    const unsigned* __restrict__ wo2h, const unsigned* __restrict__ wo2l,
    const float* __restrict__ bo2,
    const float* __restrict__ res, float* __restrict__ out,
    const unsigned* __restrict__ winh, const unsigned* __restrict__ winl,
    float* __restrict__ zs)
{
    __shared__ unsigned short Hs[2][64][136];

    int b0 = blockIdx.x * 2;
    int tid = threadIdx.x;
    int wid = tid >> 5, lane = tid & 31;
    int g = lane >> 2, t = lane & 3;
    int lr = lane & 7, lm = lane >> 3;
    int n0 = wid * 16;

    // ---- GEMM1: z @ Wo1^T (both samples) ----
    float c[4][2][4];
#pragma unroll
    for (int mi = 0; mi < 4; mi++)
#pragma unroll
        for (int nj = 0; nj < 2; nj++)
#pragma unroll
            for (int q = 0; q < 4; q++) c[mi][nj][q] = 0.f;

#pragma unroll
    for (int kt = 0; kt < 8; kt++) {
        unsigned ah[4][4], al[4][4];
#pragma unroll
        for (int mi = 0; mi < 4; mi++) {
            int s = mi >> 1, mt = mi & 1;
            afrag_pk(zh + (long)(b0 + s) * 2048, zl + (long)(b0 + s) * 2048,
                     mt * 16 + g, kt, t, 64, ah[mi], al[mi]);
        }
#pragma unroll
        for (int nj = 0; nj < 2; nj++) {
            unsigned bh[2], bl[2];
            bfrag_pk(wo1h, wo1l, n0 + nj * 8 + g, kt, t, bh, bl);
#pragma unroll
            for (int mi = 0; mi < 4; mi++)
                mma3(c[mi][nj], ah[mi], al[mi], bh, bl);
        }
    }

    // ---- epi1: +bo1, ssp, split -> Hs ----
#pragma unroll
    for (int mi = 0; mi < 4; mi++)
#pragma unroll
        for (int nj = 0; nj < 2; nj++) {
            int s = mi >> 1, mt = mi & 1;
            int R = s * 32 + mt * 16 + g;
            int k = n0 + nj * 8 + 2 * t;
            float2 bb = *(const float2*)&bo1[k];
            unsigned hi, lo;
            split2(sspf(c[mi][nj][0] + bb.x), sspf(c[mi][nj][1] + bb.y), hi, lo);
            *(unsigned*)&Hs[0][R][k] = hi;
            *(unsigned*)&Hs[1][R][k] = lo;
            split2(sspf(c[mi][nj][2] + bb.x), sspf(c[mi][nj][3] + bb.y), hi, lo);
            *(unsigned*)&Hs[0][R + 8][k] = hi;
            *(unsigned*)&Hs[1][R + 8][k] = lo;
        }
    __syncthreads();

    // ---- GEMM2: h @ Wo2^T ----
    float d[4][2][4];
#pragma unroll
    for (int mi = 0; mi < 4; mi++)
#pragma unroll
        for (int nj = 0; nj < 2; nj++)
#pragma unroll
            for (int q = 0; q < 4; q++) d[mi][nj][q] = 0.f;

#pragma unroll
    for (int kt = 0; kt < 8; kt++) {
        unsigned ah[4][4], al[4][4];
#pragma unroll
        for (int mi = 0; mi < 4; mi++) {
            int s = mi >> 1, mt = mi & 1;
            int R = s * 32 + mt * 16 + (lm & 1) * 8 + lr;
            ldm_x4(ah[mi], &Hs[0][R][kt * 16 + (lm >> 1) * 8]);
            ldm_x4(al[mi], &Hs[1][R][kt * 16 + (lm >> 1) * 8]);
        }
#pragma unroll
        for (int nj = 0; nj < 2; nj++) {
            unsigned bh[2], bl[2];
            bfrag_pk(wo2h, wo2l, n0 + nj * 8 + g, kt, t, bh, bl);
#pragma unroll
            for (int mi = 0; mi < 4; mi++)
                mma3(d[mi][nj], ah[mi], al[mi], bh, bl);
        }
    }

    if (WRITE_ZS) __syncthreads();   // all Hs reads done before plane reuse

    // ---- epi2: +bo2 + residual -> out (and Xs planes if fusing zs) ----
#pragma unroll
    for (int mi = 0; mi < 4; mi++)
#pragma unroll
        for (int nj = 0; nj < 2; nj++) {
            int s = mi >> 1, mt = mi & 1;
            int r = mt * 16 + g;
            int R = s * 32 + r;
            int k = n0 + nj * 8 + 2 * t;
            long bb4 = (long)(b0 + s) * 4096;
            float2 bb = *(const float2*)&bo2[k];
            long base0 = FIRST ? (long)(r * 128 + k) : bb4 + r * 128 + k;
            long base1 = FIRST ? (long)((r + 8) * 128 + k) : bb4 + (r + 8) * 128 + k;
            float2 r0 = *(const float2*)&res[base0];
            float2 r1 = *(const float2*)&res[base1];
            float v0 = d[mi][nj][0] + bb.x + r0.x;
            float v1 = d[mi][nj][1] + bb.y + r0.y;
            float v2 = d[mi][nj][2] + bb.x + r1.x;
            float v3 = d[mi][nj][3] + bb.y + r1.y;
            *(float2*)&out[bb4 + r * 128 + k] = make_float2(v0, v1);
            *(float2*)&out[bb4 + (r + 8) * 128 + k] = make_float2(v2, v3);
            if (WRITE_ZS) {
                unsigned hi, lo;
                split2(v0, v1, hi, lo);
                *(unsigned*)&Hs[0][R][k] = hi;
                *(unsigned*)&Hs[1][R][k] = lo;
                split2(v2, v3, hi, lo);
                *(unsigned*)&Hs[0][R + 8][k] = hi;
                *(unsigned*)&Hs[1][R + 8][k] = lo;
            }
        }

    if (WRITE_ZS) {
        __syncthreads();

        // ---- GEMM3: xs_new @ Win_next^T -> zs rows 0..31 (both samples) ----
        float e[4][2][4];
#pragma unroll
        for (int mi = 0; mi < 4; mi++)
#pragma unroll
            for (int nj = 0; nj < 2; nj++)
#pragma unroll
                for (int q = 0; q < 4; q++) e[mi][nj][q] = 0.f;

#pragma unroll
        for (int kt = 0; kt < 8; kt++) {
            unsigned ah[4][4], al[4][4];
#pragma unroll
            for (int mi = 0; mi < 4; mi++) {
                int s = mi >> 1, mt = mi & 1;
                int R = s * 32 + mt * 16 + (lm & 1) * 8 + lr;
                ldm_x4(ah[mi], &Hs[0][R][kt * 16 + (lm >> 1) * 8]);
                ldm_x4(al[mi], &Hs[1][R][kt * 16 + (lm >> 1) * 8]);
            }
#pragma unroll
            for (int nj = 0; nj < 2; nj++) {
                unsigned bh[2], bl[2];
                bfrag_pk(winh, winl, n0 + nj * 8 + g, kt, t, bh, bl);
#pragma unroll
                for (int mi = 0; mi < 4; mi++)
                    mma3(e[mi][nj], ah[mi], al[mi], bh, bl);
            }
        }

#pragma unroll
        for (int mi = 0; mi < 4; mi++)
#pragma unroll
            for (int nj = 0; nj < 2; nj++) {
                int s = mi >> 1, mt = mi & 1;
                int r = mt * 16 + g;
                int k = n0 + nj * 8 + 2 * t;
                long zb = (long)(b0 + s) * NALL;
                *(float2*)&zs[(zb + r) * 128 + k] =
                    make_float2(e[mi][nj][0], e[mi][nj][1]);
                *(float2*)&zs[(zb + r + 8) * 128 + k] =
                    make_float2(e[mi][nj][2], e[mi][nj][3]);
            }
    }
}

// ---------------------------------------------------------------------------
// Pair conv (R15 structure — verified 672.5us config) with ONE change:
// zs_s stride 132 -> 136 words (mod 32 = 8) to kill 2-way bank conflicts
// on the zj LDS.64 reads. Arithmetic bit-identical.
// ---------------------------------------------------------------------------
#define ZS_STRIDE 136
#define ZS_SMEM_BYTES (36 * ZS_STRIDE * 4)

__global__ __launch_bounds__(288, 2) void pairconv_mma_kernel(
    const float* __restrict__ dists,   // (B,32,36,32) fp32
    const unsigned* __restrict__ w1h, const unsigned* __restrict__ w1l,
    const float* __restrict__ b1g,
    const unsigned* __restrict__ w2h, const unsigned* __restrict__ w2l,
    const float* __restrict__ b2g,
    const float* __restrict__ zs,
    unsigned* __restrict__ zh, unsigned* __restrict__ zl)
{
    __shared__ unsigned short W1s[2][64][40];
    __shared__ unsigned short W2s[2][128][72];
    __shared__ float z_s[8][128];
    extern __shared__ float zs_s[];   // [36][136]

    int tid = threadIdx.x;
    int b = blockIdx.x >> 2;
    int e0g = (blockIdx.x & 3) * 8;
    int wid = tid >> 5, lane = tid & 31;
    int g = lane >> 2, t = lane & 3;
    int lr = lane & 7, lm = lane >> 3;

    // stage pre-split weight planes
    for (int idx = tid; idx < 64 * 16; idx += 288) {
        int n = idx >> 4, kp = idx & 15;
        *(unsigned*)&W1s[0][n][2 * kp] = w1h[idx];
        *(unsigned*)&W1s[1][n][2 * kp] = w1l[idx];
    }
    for (int idx = tid; idx < 128 * 32; idx += 288) {
        int n = idx >> 5, kp = idx & 31;
        *(unsigned*)&W2s[0][n][2 * kp] = w2h[idx];
        *(unsigned*)&W2s[1][n][2 * kp] = w2l[idx];
    }
    // stage zs[b] into padded smem (stride 136: conflict-free zj reads)
    {
        const float* zrow = zs + b * (36 * 128);
        for (int idx = tid; idx < 1152; idx += 288) {
            int j = idx >> 5, k4 = idx & 31;
            float4 v = *(const float4*)&zrow[j * 128 + k4 * 4];
            *(float4*)&zs_s[j * ZS_STRIDE + k4 * 4] = v;
        }
    }
    for (int idx = tid; idx < 1024; idx += 288) ((float*)z_s)[idx] = 0.f;
    __syncthreads();

    const float* drow = dists + ((long)(b * 32 + e0g) * 36) * 32;

    int e_lo = (wid * 32) / 36;
    int e_hi = (wid * 32 + 31) / 36;

    unsigned a2h[2][4][4], a2l[2][4][4];
    int ja_[2], jb_[2];
    bool skip0_[2], skip1_[2];
    bool hi0_[2], hi1_[2];

#pragma unroll
    for (int i = 0; i < 2; i++) {
        int mb = wid * 32 + i * 16;
        int r0 = mb + g, r1 = r0 + 8;
        int ea = r0 / 36, ja = r0 - 36 * ea;
        int eb = r1 / 36, jb = r1 - 36 * eb;
        ja_[i] = ja; jb_[i] = jb;
        skip0_[i] = (ja == e0g + ea);
        skip1_[i] = (jb == e0g + eb);
        hi0_[i] = (ea != e_lo);
        hi1_[i] = (eb != e_lo);

        // A-fragments of db (fp32 load + split)
        unsigned ah[2][4], al[2][4];
#pragma unroll
        for (int kt = 0; kt < 2; kt++) {
            int col = 16 * kt + 2 * t;
            float2 v00 = *(const float2*)&drow[(ea * 36 + ja) * 32 + col];
            float2 v10 = *(const float2*)&drow[(eb * 36 + jb) * 32 + col];
            float2 v01 = *(const float2*)&drow[(ea * 36 + ja) * 32 + col + 8];
            float2 v11 = *(const float2*)&drow[(eb * 36 + jb) * 32 + col + 8];
            split2(v00.x, v00.y, ah[kt][0], al[kt][0]);
            split2(v10.x, v10.y, ah[kt][1], al[kt][1]);
            split2(v01.x, v01.y, ah[kt][2], al[kt][2]);
            split2(v11.x, v11.y, ah[kt][3], al[kt][3]);
        }

        float c1[8][4];
#pragma unroll
        for (int nt = 0; nt < 8; nt++) {
            unsigned bh[4], bl[4];
            ldm_x4(bh, &W1s[0][nt * 8 + lr][8 * lm]);
            ldm_x4(bl, &W1s[1][nt * 8 + lr][8 * lm]);
            float cA[4] = {0.f, 0.f, 0.f, 0.f};
            float cB[4] = {0.f, 0.f, 0.f, 0.f};
            mma3(cA, ah[0], al[0], &bh[0], &bl[0]);
            mma3(cB, ah[1], al[1], &bh[2], &bl[2]);
#pragma unroll
            for (int q = 0; q < 4; q++) c1[nt][q] = cA[q] + cB[q];
        }

#pragma unroll
        for (int kt2 = 0; kt2 < 4; kt2++) {
            int n0 = 2 * kt2, n1 = n0 + 1;
            float2 bb0 = *(const float2*)&b1g[n0 * 8 + 2 * t];
            float2 bb1 = *(const float2*)&b1g[n1 * 8 + 2 * t];
            split2(sspf(c1[n0][0] + bb0.x), sspf(c1[n0][1] + bb0.y), a2h[i][kt2][0], a2l[i][kt2][0]);
            split2(sspf(c1[n0][2] + bb0.x), sspf(c1[n0][3] + bb0.y), a2h[i][kt2][1], a2l[i][kt2][1]);
            split2(sspf(c1[n1][0] + bb1.x), sspf(c1[n1][1] + bb1.y), a2h[i][kt2][2], a2l[i][kt2][2]);
            split2(sspf(c1[n1][2] + bb1.x), sspf(c1[n1][3] + bb1.y), a2h[i][kt2][3], a2l[i][kt2][3]);
        }
    }

#pragma unroll
    for (int half = 0; half < 2; half++) {
#pragma unroll
        for (int nt = 0; nt < 8; nt++) {
            int nn = half * 64 + nt * 8;
            int k0 = nn + 2 * t;

            unsigned h0[4], h1[4], l0[4], l1[4];
            ldm_x4(h0, &W2s[0][nn + lr][8 * lm]);
            ldm_x4(h1, &W2s[0][nn + lr][32 + 8 * lm]);
            ldm_x4(l0, &W2s[1][nn + lr][8 * lm]);
            ldm_x4(l1, &W2s[1][nn + lr][32 + 8 * lm]);
            float2 bb = *(const float2*)&b2g[k0];

            float acc0[2] = {0.f, 0.f};
            float acc1[2] = {0.f, 0.f};

#pragma unroll
            for (int i = 0; i < 2; i++) {
                float2 zj0 = skip0_[i] ? make_float2(0.f, 0.f)
                                       : *(const float2*)&zs_s[ja_[i] * ZS_STRIDE + k0];
                float2 zj1 = skip1_[i] ? make_float2(0.f, 0.f)
                                       : *(const float2*)&zs_s[jb_[i] * ZS_STRIDE + k0];

                float cA[4] = {0.f, 0.f, 0.f, 0.f};
                float cB[4] = {0.f, 0.f, 0.f, 0.f};
                mma3(cA, a2h[i][0], a2l[i][0], &h0[0], &l0[0]);
                mma3(cA, a2h[i][1], a2l[i][1], &h0[2], &l0[2]);
                mma3(cB, a2h[i][2], a2l[i][2], &h1[0], &l1[0]);
                mma3(cB, a2h[i][3], a2l[i][3], &h1[2], &l1[2]);

                float p0 = (cA[0] + cB[0] + bb.x) * zj0.x;
                float p1 = (cA[1] + cB[1] + bb.y) * zj0.y;
                float p2 = (cA[2] + cB[2] + bb.x) * zj1.x;
                float p3 = (cA[3] + cB[3] + bb.y) * zj1.y;
                if (hi0_[i]) { acc1[0] += p0; acc1[1] += p1; }
                else         { acc0[0] += p0; acc0[1] += p1; }
                if (hi1_[i]) { acc1[0] += p2; acc1[1] += p3; }
                else         { acc0[0] += p2; acc0[1] += p3; }
            }

#pragma unroll
            for (int q = 0; q < 2; q++) {
                float v = acc0[q];
                v += __shfl_down_sync(0xffffffffu, v, 16);
                v += __shfl_down_sync(0xffffffffu, v, 8);
                v += __shfl_down_sync(0xffffffffu, v, 4);
                float w = acc1[q];
                w += __shfl_down_sync(0xffffffffu, w, 16);
                w += __shfl_down_sync(0xffffffffu, w, 8);
                w += __shfl_down_sync(0xffffffffu, w, 4);
                if (lane < 4) {
                    int k = nn + 2 * lane + q;
                    atomicAdd(&z_s[e_lo][k], v);
                    if (e_hi != e_lo) atomicAdd(&z_s[e_hi][k], w);
                }
            }
        }
    }

    __syncthreads();
    // write z as packed bf16 planes (fragment-ready perm layout, 64 words/row)
    for (int idx = tid; idx < 512; idx += 288) {
        int e = idx >> 6, w = idx & 63;
        int kt = w >> 3, i2 = w & 7, tt = i2 >> 1, h = i2 & 1;
        int c0 = kt * 16 + 2 * tt + 8 * h;
        unsigned hi, lo;
        split2(z_s[e][c0], z_s[e][c0 + 1], hi, lo);
        long off = (long)(b * 32 + e0g + e) * 64 + w;
        zh[off] = hi;
        zl[off] = lo;
    }
}

// ---------------------------------------------------------------------------
// launch
// ---------------------------------------------------------------------------
extern "C" void kernel_launch(void* const* d_in, const int* in_sizes, int n_in,
                              void* d_out, int out_size)
{
    const float* dists = (const float*)d_in[0];
    const float* emb_e = (const float*)d_in[1];
    const float* emb_n = (const float*)d_in[2];
    const float* w1    = (const float*)d_in[3];
    const float* b1    = (const float*)d_in[4];
    const float* w2    = (const float*)d_in[5];
    const float* b2    = (const float*)d_in[6];
    const float* win   = (const float*)d_in[7];
    const float* wo1   = (const float*)d_in[8];
    const float* bo1   = (const float*)d_in[9];
    const float* wo2   = (const float*)d_in[10];
    const float* bo2   = (const float*)d_in[11];
    float* out = (float*)d_out;

    float *xs, *zsv;
    unsigned *zh, *zl, *eh, *el;
    unsigned *winh, *winl, *wo1h, *wo1l, *wo2h, *wo2l;
    unsigned *w1h, *w1l, *w2h, *w2l;
    cudaGetSymbolAddress((void**)&xs,   g_xs);
    cudaGetSymbolAddress((void**)&zsv,  g_zs);
    cudaGetSymbolAddress((void**)&zh,   g_zh);
    cudaGetSymbolAddress((void**)&zl,   g_zl);
    cudaGetSymbolAddress((void**)&eh,   g_eh);
    cudaGetSymbolAddress((void**)&el,   g_el);
    cudaGetSymbolAddress((void**)&winh, g_winh);
    cudaGetSymbolAddress((void**)&winl, g_winl);
    cudaGetSymbolAddress((void**)&wo1h, g_wo1h);
    cudaGetSymbolAddress((void**)&wo1l, g_wo1l);
    cudaGetSymbolAddress((void**)&wo2h, g_wo2h);
    cudaGetSymbolAddress((void**)&wo2l, g_wo2l);
    cudaGetSymbolAddress((void**)&w1h,  g_w1h);
    cudaGetSymbolAddress((void**)&w1l,  g_w1l);
    cudaGetSymbolAddress((void**)&w2h,  g_w2h);
    cudaGetSymbolAddress((void**)&w2l,  g_w2l);

    // ---- single fused prep launch ----
    pack_all_kernel<<<(PACK_ALL_TOTAL + 255) / 256, 256>>>(
        w1, w2, emb_e, win, wo1, wo2, emb_n,
        w1h, w1l, w2h, w2l, eh, el,
        winh, winl, wo1h, wo1l, wo2h, wo2l, zsv);

    // t=0 zs linear (xs == emb broadcast)
    zslin_first_kernel<<<BATCH, 256>>>(eh, el, winh, winl, zsv);

    // t = 0
    pairconv_mma_kernel<<<BATCH * 4, 288, ZS_SMEM_BYTES>>>(
        dists, w1h, w1l, b1, w2h, w2l, b2, zsv, zh, zl);
    outmlp_mma_kernel<true, true><<<BATCH / 2, 256>>>(
        zh, zl, wo1h, wo1l, bo1, wo2h, wo2l, bo2, emb_e, xs,
        winh + 1 * 8192, winl + 1 * 8192, zsv);

    // t = 1
    pairconv_mma_kernel<<<BATCH * 4, 288, ZS_SMEM_BYTES>>>(
        dists, w1h + 1024, w1l + 1024, b1 + HIDK,
        w2h + 4096, w2l + 4096, b2 + KDIM, zsv, zh, zl);
    outmlp_mma_kernel<false, true><<<BATCH / 2, 256>>>(
        zh, zl, wo1h + 8192, wo1l + 8192, bo1 + HIDO,
        wo2h + 8192, wo2l + 8192, bo2 + EDIM, xs, xs,
        winh + 2 * 8192, winl + 2 * 8192, zsv);

    // t = 2: final, write d_out
    pairconv_mma_kernel<<<BATCH * 4, 288, ZS_SMEM_BYTES>>>(
        dists, w1h + 2048, w1l + 2048, b1 + 2 * HIDK,
        w2h + 8192, w2l + 8192, b2 + 2 * KDIM, zsv, zh, zl);
    outmlp_mma_kernel<false, false><<<BATCH / 2, 256>>>(
        zh, zl, wo1h + 2 * 8192, wo1l + 2 * 8192, bo1 + 2 * HIDO,
        wo2h + 2 * 8192, wo2l + 2 * 8192, bo2 + 2 * EDIM, xs, out,
        nullptr, nullptr, nullptr);
}